// round 17
// baseline (speedup 1.0000x reference)
#include <cuda_runtime.h>
#include <cuda_fp16.h>

#define NMAX   100000
#define EMAX   1600000
#define EPAD   2000000          // padded CSR capacity (E + 3N max)
#define CIN_   128
#define COUT_  64
#define SCAN_C 1024
#define NBLK_MAX 128
#define DUMMY_OFF (NMAX << 7)   // byte offset of the permanently-zero H row

// Scratch (device globals — no allocation allowed). 16B alignment is REQUIRED
// on every array accessed through a vector type, AND on shared arrays read
// via 128-bit LDS (see fused kernel).
// Invariants at entry (restored each call; static zero-init on first call):
//   g_deg == 0, g_scan_cnt == 0, g_cnt0 == 0, g_sync0 == 0, g_sync1 == 0,
//   g_H2 row NMAX stays zero.
__device__ __align__(16) __half2 g_H2[(NMAX + 1) * (COUT_ / 2)]; // Hs fp16; row NMAX = zeros
__device__ float   g_dinv[NMAX];
__device__ int     g_deg[NMAX];
__device__ int     g_rowoff[NMAX];             // block-local PADDED exclusive prefix
__device__ int     g_boff[NBLK_MAX];           // per-1024-chunk global offset
__device__ int     g_bsum[NBLK_MAX];
__device__ __align__(16) int g_pos[EMAX];
__device__ __align__(16) int g_edge[EPAD];     // PRE-SHIFTED byte offsets (src<<7), CSR by dst
__device__ int     g_scan_cnt;
__device__ int     g_cnt0;                     // degpos completion counter
__device__ int     g_sync0;                    // degpos-complete flag
__device__ int     g_sync1;                    // scan-complete flag
__device__ int     g_total_pad;                // total padded edge count

// ---------------------------------------------------------------------------
// acquire-spin helpers (producers use st.release)
// ---------------------------------------------------------------------------
__device__ __forceinline__ void wait_flag(int* flag) {
    if (threadIdx.x == 0) {
        int f;
        do {
            asm volatile("ld.acquire.gpu.global.b32 %0, [%1];"
                         : "=r"(f) : "l"(flag) : "memory");
            if (!f) __nanosleep(128);
        } while (!f);
    }
    __syncthreads();
}

// ---------------------------------------------------------------------------
// mega-kernel: 5 roles by block range, dependency-ordered (spin only on
// strictly lower-indexed blocks; lowest role never spins -> deadlock-free):
//   [0, ND)        degpos: deg atomics + slot record; last block releases sync0
//   [ND, +NSCAN)   scan  : waits sync0; padded prefix + dinv + boff; releases sync1
//   [.., +NG)      gemm  : main loop independent; waits sync1 only at epilogue
//   [.., +NF)      fill  : waits sync1; edge[off(d)+pos] = src<<7
//   [.., +NP)      pad   : waits sync1; dummy slots + deg reset
// ---------------------------------------------------------------------------
#define FMA2(d, a, b) asm("fma.rn.f32x2 %0, %1, %2, %3;" \
                          : "=l"(d) : "l"(a), "l"(b), "l"(d))

__global__ __launch_bounds__(256) void mega_kernel(
    const float* __restrict__ X, const float* __restrict__ W,
    const float* __restrict__ bias,
    const int* __restrict__ src, const int* __restrict__ dst,
    int n, int E, int ND, int NSCAN, int NG, int NF)
{
    const int tid = threadIdx.x;
    const int bid = blockIdx.x;

    // ===================== degpos role =====================
    if (bid < ND) {
        int base = (bid * 256 + tid) * 4;
        if (base + 3 < E) {
            int4 d = *(const int4*)(dst + base);
            int4 p;
            p.x = atomicAdd(&g_deg[d.x], 1);
            p.y = atomicAdd(&g_deg[d.y], 1);
            p.z = atomicAdd(&g_deg[d.z], 1);
            p.w = atomicAdd(&g_deg[d.w], 1);
            *(int4*)(g_pos + base) = p;
        } else {
            for (int i = base; i < E; i++)
                g_pos[i] = atomicAdd(&g_deg[dst[i]], 1);
        }
        __syncthreads();
        if (tid == 0) {
            __threadfence();
            int old = atomicAdd(&g_cnt0, 1);
            if (old == ND - 1) {
                g_cnt0 = 0;                      // restore invariant
                __threadfence();
                asm volatile("st.release.gpu.global.b32 [%0], %1;"
                             :: "l"(&g_sync0), "r"(1) : "memory");
            }
        }
        return;
    }

    // ===================== scan role =====================
    if (bid < ND + NSCAN) {
        wait_flag(&g_sync0);
        __shared__ __align__(16) int wsum[8];
        __shared__ int is_last;
        const int b    = bid - ND;
        const int base = b * SCAN_C + tid * 4;
        const int lane = tid & 31;
        const int warp = tid >> 5;

        int vp[4];
        #pragma unroll
        for (int i = 0; i < 4; i++) {
            int idx = base + i;
            int tv = (idx < n) ? g_deg[idx] : 0;
            if (idx < n) g_dinv[idx] = rsqrtf(1.0f + (float)tv);
            vp[i] = (tv + 3) & ~3;               // padded degree
        }
        int tsum = vp[0] + vp[1] + vp[2] + vp[3];

        int x = tsum;
        #pragma unroll
        for (int off = 1; off < 32; off <<= 1) {
            int y = __shfl_up_sync(0xFFFFFFFFu, x, off);
            if (lane >= off) x += y;
        }
        if (lane == 31) wsum[warp] = x;
        __syncthreads();
        if (tid == 0) {
            int run = 0;
            #pragma unroll
            for (int w = 0; w < 8; w++) { int t = wsum[w]; wsum[w] = run; run += t; }
            g_bsum[b] = run;
        }
        __syncthreads();

        int run = wsum[warp] + x - tsum;
        #pragma unroll
        for (int i = 0; i < 4; i++) {
            int idx = base + i;
            if (idx < n) g_rowoff[idx] = run;
            run += vp[i];
        }

        __syncthreads();
        if (tid == 0) {
            __threadfence();
            int old = atomicAdd(&g_scan_cnt, 1);
            is_last = (old == NSCAN - 1);
        }
        __syncthreads();
        if (is_last) {
            __threadfence();
            __shared__ __align__(16) int sp[NBLK_MAX];
            if (tid < NBLK_MAX) sp[tid] = (tid < NSCAN) ? g_bsum[tid] : 0;
            __syncthreads();
            #pragma unroll
            for (int s = 1; s < NBLK_MAX; s <<= 1) {
                int vv = 0;
                if (tid < NBLK_MAX && tid >= s) vv = sp[tid - s];
                __syncthreads();
                if (tid < NBLK_MAX) sp[tid] += vv;
                __syncthreads();
            }
            if (tid < NSCAN) g_boff[tid] = (tid == 0) ? 0 : sp[tid - 1];
            if (tid == 0) {
                g_total_pad = sp[NSCAN - 1];
                g_scan_cnt  = 0;                 // restore invariant
            }
            __syncthreads();
            if (tid == 0) {
                __threadfence();
                asm volatile("st.release.gpu.global.b32 [%0], %1;"
                             :: "l"(&g_sync1), "r"(1) : "memory");
            }
        }
        return;
    }

    // ===================== gemm role =====================
    if (bid < ND + NSCAN + NG) {
        __shared__ __align__(16) float2 Xs2[16][130];
        __shared__ __align__(16) float  Ws[16][64];

        const int tcol = tid & 15;
        const int trow = tid >> 4;
        const int row0 = (bid - ND - NSCAN) * 128;

        unsigned long long acc[8][2];
        #pragma unroll
        for (int r = 0; r < 8; r++) { acc[r][0] = 0ull; acc[r][1] = 0ull; }

        for (int k0 = 0; k0 < CIN_; k0 += 16) {
            #pragma unroll
            for (int p = 0; p < 2; p++) {
                int r  = p * 64 + (tid >> 2);
                int kq = tid & 3;
                int rr = row0 + r;
                const float* xp = X + (long)(rr < n ? rr : 0) * CIN_ + k0 + kq * 4;
                float4 v = *(const float4*)xp;
                Xs2[kq * 4 + 0][r] = make_float2(v.x, v.x);
                Xs2[kq * 4 + 1][r] = make_float2(v.y, v.y);
                Xs2[kq * 4 + 2][r] = make_float2(v.z, v.z);
                Xs2[kq * 4 + 3][r] = make_float2(v.w, v.w);
            }
            {
                int k    = tid >> 4;
                int colq = tid & 15;
                float4 v = *(const float4*)(W + (long)(k0 + k) * COUT_ + colq * 4);
                *(float4*)&Ws[k][colq * 4] = v;
            }
            __syncthreads();

            #pragma unroll
            for (int kk = 0; kk < 16; kk++) {
                ulonglong2 a01 = *(const ulonglong2*)&Xs2[kk][trow * 8 + 0];
                ulonglong2 a23 = *(const ulonglong2*)&Xs2[kk][trow * 8 + 2];
                ulonglong2 a45 = *(const ulonglong2*)&Xs2[kk][trow * 8 + 4];
                ulonglong2 a67 = *(const ulonglong2*)&Xs2[kk][trow * 8 + 6];
                ulonglong2 b   = *(const ulonglong2*)&Ws[kk][tcol * 4];
                FMA2(acc[0][0], a01.x, b.x);  FMA2(acc[0][1], a01.x, b.y);
                FMA2(acc[1][0], a01.y, b.x);  FMA2(acc[1][1], a01.y, b.y);
                FMA2(acc[2][0], a23.x, b.x);  FMA2(acc[2][1], a23.x, b.y);
                FMA2(acc[3][0], a23.y, b.x);  FMA2(acc[3][1], a23.y, b.y);
                FMA2(acc[4][0], a45.x, b.x);  FMA2(acc[4][1], a45.x, b.y);
                FMA2(acc[5][0], a45.y, b.x);  FMA2(acc[5][1], a45.y, b.y);
                FMA2(acc[6][0], a67.x, b.x);  FMA2(acc[6][1], a67.x, b.y);
                FMA2(acc[7][0], a67.y, b.x);  FMA2(acc[7][1], a67.y, b.y);
            }
            __syncthreads();
        }

        wait_flag(&g_sync1);                     // dinv ready

        float2 bb0 = *(const float2*)(bias + tcol * 4);
        float2 bb1 = *(const float2*)(bias + tcol * 4 + 2);
        #pragma unroll
        for (int r = 0; r < 8; r++) {
            int row = row0 + trow * 8 + r;
            if (row < n) {
                float di = g_dinv[row];
                float2 lo = *(const float2*)&acc[r][0];
                float2 hi = *(const float2*)&acc[r][1];
                __half2 h0 = __floats2half2_rn((lo.x + bb0.x) * di, (lo.y + bb0.y) * di);
                __half2 h1 = __floats2half2_rn((hi.x + bb1.x) * di, (hi.y + bb1.y) * di);
                g_H2[(long)row * 32 + tcol * 2]     = h0;
                g_H2[(long)row * 32 + tcol * 2 + 1] = h1;
            }
        }
        return;
    }

    // ===================== fill role =====================
    if (bid < ND + NSCAN + NG + NF) {
        wait_flag(&g_sync1);
        int cid  = bid - ND - NSCAN - NG;
        int base = (cid * 256 + tid) * 4;
        if (base + 3 < E) {
            int4 s = *(const int4*)(src + base);
            int4 d = *(const int4*)(dst + base);
            int4 p = *(const int4*)(g_pos + base);
            int o0 = g_rowoff[d.x] + g_boff[d.x >> 10] + p.x;
            int o1 = g_rowoff[d.y] + g_boff[d.y >> 10] + p.y;
            int o2 = g_rowoff[d.z] + g_boff[d.z >> 10] + p.z;
            int o3 = g_rowoff[d.w] + g_boff[d.w >> 10] + p.w;
            g_edge[o0] = s.x << 7;               // pre-shifted byte offsets
            g_edge[o1] = s.y << 7;
            g_edge[o2] = s.z << 7;
            g_edge[o3] = s.w << 7;
        } else {
            for (int i = base; i < E; i++) {
                int d = dst[i];
                g_edge[g_rowoff[d] + g_boff[d >> 10] + g_pos[i]] = src[i] << 7;
            }
        }
        return;
    }

    // ===================== pad role =====================
    {
        wait_flag(&g_sync1);
        int cid = bid - ND - NSCAN - NG - NF;
        int i = cid * 256 + tid;
        if (i < n) {
            int d0 = g_deg[i];
            int r  = g_rowoff[i] + g_boff[i >> 10];
            int e1 = r + ((d0 + 3) & ~3);
            for (int k = r + d0; k < e1; k++) g_edge[k] = DUMMY_OFF;
            g_deg[i] = 0;                        // restore invariant
        }
    }
}

// ---------------------------------------------------------------------------
// gather: one warp per node, one half2 per lane (64 cols).
//    Padded CSR: count multiple of 4, 16B-aligned -> pure int4 index batches,
//    pre-shifted byte offsets, tree-of-8 HADD2, single widen per 8 edges.
//    Also restores the sync flags for the next call.
//    out[d] = relu( dinv[d] * ( Hs[d] + sum_e Hs[src] ) )
// ---------------------------------------------------------------------------
__global__ __launch_bounds__(256) void gather_kernel(float* __restrict__ out, int n) {
    if (blockIdx.x == 0 && threadIdx.x == 0) {
        g_sync0 = 0;                             // restore invariants
        g_sync1 = 0;
    }
    int node = (blockIdx.x * 256 + threadIdx.x) >> 5;
    if (node >= n) return;
    int lane = threadIdx.x & 31;

    float dd = g_dinv[node];
    int   r0 = g_rowoff[node] + g_boff[node >> 10];
    int   r1 = (node + 1 < n) ? (g_rowoff[node + 1] + g_boff[(node + 1) >> 10])
                              : g_total_pad;
    int   m4 = (r1 - r0) >> 2;                   // int4 batches (exact)

    const char* hbB = (const char*)g_H2 + lane * 4;
    float2 acc = __half22float2(*(const __half2*)(hbB + ((long)node << 7)));

    const int4* ep4 = (const int4*)(g_edge + r0);
    int q = 0;
    for (; q + 2 <= m4; q += 2) {
        int4 A = __ldg(ep4 + q);
        int4 B = __ldg(ep4 + q + 1);
        __half2 a0 = __ldg((const __half2*)(hbB + A.x));
        __half2 a1 = __ldg((const __half2*)(hbB + A.y));
        __half2 a2 = __ldg((const __half2*)(hbB + A.z));
        __half2 a3 = __ldg((const __half2*)(hbB + A.w));
        __half2 a4 = __ldg((const __half2*)(hbB + B.x));
        __half2 a5 = __ldg((const __half2*)(hbB + B.y));
        __half2 a6 = __ldg((const __half2*)(hbB + B.z));
        __half2 a7 = __ldg((const __half2*)(hbB + B.w));
        __half2 s01 = __hadd2(a0, a1), s23 = __hadd2(a2, a3);
        __half2 s45 = __hadd2(a4, a5), s67 = __hadd2(a6, a7);
        __half2 s03 = __hadd2(s01, s23), s47 = __hadd2(s45, s67);
        __half2 s   = __hadd2(s03, s47);
        float2 f = __half22float2(s);
        acc.x += f.x;  acc.y += f.y;
    }
    if (q < m4) {
        int4 A = __ldg(ep4 + q);
        __half2 a0 = __ldg((const __half2*)(hbB + A.x));
        __half2 a1 = __ldg((const __half2*)(hbB + A.y));
        __half2 a2 = __ldg((const __half2*)(hbB + A.z));
        __half2 a3 = __ldg((const __half2*)(hbB + A.w));
        __half2 s01 = __hadd2(a0, a1), s23 = __hadd2(a2, a3);
        __half2 s   = __hadd2(s01, s23);
        float2 f = __half22float2(s);
        acc.x += f.x;  acc.y += f.y;
    }

    float2 o = make_float2(fmaxf(acc.x * dd, 0.0f), fmaxf(acc.y * dd, 0.0f));
    *(float2*)&out[(long)node * COUT_ + lane * 2] = o;
}

// ---------------------------------------------------------------------------
extern "C" void kernel_launch(void* const* d_in, const int* in_sizes, int n_in,
                              void* d_out, int out_size)
{
    const float* X    = (const float*)d_in[0];   // (N, 128)
    const float* W    = (const float*)d_in[1];   // (128, 64)
    const float* bias = (const float*)d_in[2];   // (64,)
    const int*   src  = (const int*)d_in[3];     // (E,)
    const int*   dst  = (const int*)d_in[4];     // (E,)
    float*       out  = (float*)d_out;           // (N, 64)

    const int n = in_sizes[0] / CIN_;
    const int E = in_sizes[3];

    const int ND    = (E + 1023) / 1024;           // degpos chunks (1563)
    const int NSCAN = (n + SCAN_C - 1) / SCAN_C;   // 98
    const int NG    = (n + 127) / 128;             // 782
    const int NF    = (E + 1023) / 1024;           // 1563
    const int NP    = (n + 255) / 256;             // 391

    mega_kernel<<<ND + NSCAN + NG + NF + NP, 256>>>(X, W, bias, src, dst,
                                                    n, E, ND, NSCAN, NG, NF);
    gather_kernel<<<(int)(((long)n * 32 + 255) / 256), 256>>>(out, n);
}